// round 5
// baseline (speedup 1.0000x reference)
#include <cuda_runtime.h>
#include <cstdint>

// MagNorm: per-channel EMA mean/var over T, normalize each step.
//   mu_t  = a*mu_{t-1} + (1-a)*x_t
//   var_t = a*var_{t-1} + (1-a)*(x_t - mu_t)^2
//   y_t   = (x_t - mu_t) * rsqrt(var_t)
// identity: x_t - mu_t = a*(x_t - mu_{t-1}).
//
// x [32, 4096, 481] f32, mu0 [32, 481] f32. Thread = channel, lane = f.
//
// R4 post-mortem: doubling warps did NOT raise HBM throughput (4.0 TB/s
// plateau) — per-SM load queue was already overflowing; every extra in-flight
// LDG just queued. R5 attacks the latency itself: prefetch.global.L2 issued
// 8 chunks (256 steps, ~7k cyc) ahead turns demand LDGs into ~240-cyc L2
// hits, which the existing 3-chunk register lookahead fully covers.
// Prefetch footprint 481*256*128B ~ 15MB << 126MB L2.

#ifndef MN_B
#define MN_B 32
#define MN_T 4096
#define MN_F 481
#endif

__global__ void __launch_bounds__(32)
magnorm_kernel(const float* __restrict__ x,
               const float* __restrict__ mu0,
               float* __restrict__ out)
{
    constexpr int T   = MN_T;
    constexpr int F   = MN_F;
    constexpr int U   = 32;              // chunk size
    constexpr int NB  = 4;               // register pipeline depth
    constexpr int NCH = T / U;           // 128 chunks
    constexpr int PD  = 8;               // prefetch distance in chunks (256 steps)

    const int gid = blockIdx.x * blockDim.x + threadIdx.x;
    if (gid >= MN_B * MN_F) return;

    const int b = gid / F;
    const int f = gid - b * F;

    const float a  = 0.99f;
    const float om = 0.01f;

    float mu  = mu0[gid];
    float var = 1600.0f;                 // 40^2

    const size_t base = (size_t)b * T * F + (size_t)f;
    const float* __restrict__ px = x   + base;
    float*       __restrict__ py = out + base;

    float buf[NB][U];                    // static indexing only -> registers

    // Prologue: prefetch chunks [NB-1, NB-1+PD) into L2 so the register
    // pipeline's first demand loads beyond the prologue already hit L2.
#pragma unroll 1
    for (int c = NB - 1; c < NB - 1 + PD; c++) {
        const float* pp = px + (size_t)c * U * F;
#pragma unroll
        for (int i = 0; i < U; i++)
            asm volatile("prefetch.global.L2 [%0];" :: "l"(pp + (size_t)i * F));
    }

    // Prologue: demand-load chunks 0 .. NB-2 into buffers 0 .. NB-2.
    const float* pn = px;
#pragma unroll
    for (int s = 0; s < NB - 1; s++) {
#pragma unroll
        for (int i = 0; i < U; i++)
            buf[s][i] = __ldcs(pn + (size_t)i * F);
        pn += (size_t)U * F;
    }

    for (int g = 0; g < NCH; g += NB) {
#pragma unroll
        for (int s = 0; s < NB; s++) {
            constexpr int ls = NB - 1;           // register lookahead (chunks)
            const int cload = g + s + ls;        // chunk being demand-loaded

            // L2 prefetch PD chunks ahead of the demand load.
            if (cload + PD < NCH) {
                const float* pp = pn + (size_t)PD * U * F;
#pragma unroll
                for (int i = 0; i < U; i++)
                    asm volatile("prefetch.global.L2 [%0];"
                                 :: "l"(pp + (size_t)i * F));
            }

            // Demand loads for chunk cload into the just-freed buffer slot.
            if (cload < NCH) {
#pragma unroll
                for (int i = 0; i < U; i++)
                    buf[(s + ls) % NB][i] = __ldcs(pn + (size_t)i * F);
                pn += (size_t)U * F;
            }

            // Consume chunk g + s from buffer s while loads/prefetches fly.
#pragma unroll
            for (int i = 0; i < U; i++) {
                const float xv = buf[s][i];
                const float e  = xv - mu;        // x_t - mu_{t-1}
                mu = fmaf(om, e, mu);            // = a*mu + (1-a)*x
                const float d = a * e;           // = x_t - mu_t
                var = fmaf(a, var, om * (d * d));
                __stcs(py + (size_t)i * F, d * rsqrtf(var));
            }
            py += (size_t)U * F;
        }
    }
}

extern "C" void kernel_launch(void* const* d_in, const int* in_sizes, int n_in,
                              void* d_out, int out_size)
{
    const float* x   = (const float*)d_in[0];
    const float* mu0 = (const float*)d_in[1];
    if (n_in >= 2 && in_sizes[0] < in_sizes[1]) {
        x   = (const float*)d_in[1];
        mu0 = (const float*)d_in[0];
    }
    float* out = (float*)d_out;

    const int channels = MN_B * MN_F;                  // 15392
    const int block = 32;                              // 1 warp/block
    const int grid  = (channels + block - 1) / block;  // 481
    magnorm_kernel<<<grid, block>>>(x, mu0, out);
}